// round 1
// baseline (speedup 1.0000x reference)
#include <cuda_runtime.h>
#include <cuda_bf16.h>

// ---------------------------------------------------------------------------
// SimplifiedMamba2Block: LN -> GEMM1(+clip,split,tanh) -> sequential SSM scan
//                        -> GEMM2(+clip) -> LN
// Shapes: x (4,2048,1024); W_in (3072,1024); W_out (1024,1536);
//         A_log/B/C (1536,8); ln params (1024,)
// ---------------------------------------------------------------------------

#define NTOK   8192          // 4*2048
#define DM     1024
#define DI     1536
#define DS     8
#define NDI2   3072          // 2*DI
#define SEQ    2048
#define NB     4

#define CLIP5(v) fminf(fmaxf((v), -5.0f), 5.0f)

// scratch (allocation-free rule: __device__ globals)
__device__ float g_xnorm[NTOK * DM];   // LN(x)
__device__ float g_xssm [NTOK * DI];   // x_ssm, later overwritten with y*tanh(gate)
__device__ float g_gate [NTOK * DI];   // tanh(clip(gate))
__device__ float g_out1 [NTOK * DM];   // pre-LN output

// ---------------------------------------------------------------------------
// LayerNorm over last dim (1024). One block per token row, 256 threads,
// 4 elems (one float4) per thread.
// ---------------------------------------------------------------------------
__global__ __launch_bounds__(256) void ln_kernel(
    const float* __restrict__ in, const float* __restrict__ g,
    const float* __restrict__ b, float* __restrict__ out)
{
    __shared__ float s_sum[8], s_sq[8];
    int row = blockIdx.x;
    int tid = threadIdx.x;
    const float4 v = *(const float4*)(in + (size_t)row * DM + tid * 4);

    float sum = v.x + v.y + v.z + v.w;
    float sq  = v.x*v.x + v.y*v.y + v.z*v.z + v.w*v.w;
    // warp reduce
    #pragma unroll
    for (int o = 16; o > 0; o >>= 1) {
        sum += __shfl_xor_sync(0xffffffffu, sum, o);
        sq  += __shfl_xor_sync(0xffffffffu, sq , o);
    }
    int wid = tid >> 5, lid = tid & 31;
    if (lid == 0) { s_sum[wid] = sum; s_sq[wid] = sq; }
    __syncthreads();
    if (wid == 0) {
        float a = (lid < 8) ? s_sum[lid] : 0.f;
        float c = (lid < 8) ? s_sq [lid] : 0.f;
        #pragma unroll
        for (int o = 4; o > 0; o >>= 1) {
            a += __shfl_xor_sync(0xffffffffu, a, o);
            c += __shfl_xor_sync(0xffffffffu, c, o);
        }
        if (lid == 0) { s_sum[0] = a; s_sq[0] = c; }
    }
    __syncthreads();
    float mean = s_sum[0] * (1.0f / DM);
    float var  = s_sq[0] * (1.0f / DM) - mean * mean;
    float rstd = rsqrtf(var + 1e-5f);

    const float4 gv = *(const float4*)(g + tid * 4);
    const float4 bv = *(const float4*)(b + tid * 4);
    float4 o4;
    o4.x = (v.x - mean) * rstd * gv.x + bv.x;
    o4.y = (v.y - mean) * rstd * gv.y + bv.y;
    o4.z = (v.z - mean) * rstd * gv.z + bv.z;
    o4.w = (v.w - mean) * rstd * gv.w + bv.w;
    *(float4*)(out + (size_t)row * DM + tid * 4) = o4;
}

// ---------------------------------------------------------------------------
// Tiled SGEMM: Cmn = sum_k A[m][k] * W[n][k]   (A: MxK rm, W: NxK rm)
// BM=BN=128, BK=16, 256 threads, 8x8 per-thread microtile.
// MODE 0: GEMM1 epilogue -> clip; cols<DI to x_ssm, cols>=DI tanh->gate
// MODE 1: GEMM2 epilogue -> clip -> out0
// M, N, K are multiples of the tile sizes (8192; 3072/1024; 1024/1536).
// ---------------------------------------------------------------------------
template<int MODE>
__global__ __launch_bounds__(256) void gemm_kernel(
    const float* __restrict__ A, const float* __restrict__ W,
    int M, int N, int K,
    float* __restrict__ out0, float* __restrict__ out1)
{
    constexpr int BM = 128, BN = 128, BK = 16;
    __shared__ float As[BK][BM + 4];
    __shared__ float Bs[BK][BN + 4];

    const int bm = blockIdx.y * BM;
    const int bn = blockIdx.x * BN;
    const int tid = threadIdx.x;
    const int tx = tid & 15;        // 0..15 -> n
    const int ty = tid >> 4;        // 0..15 -> m

    float acc[8][8];
    #pragma unroll
    for (int i = 0; i < 8; i++)
        #pragma unroll
        for (int j = 0; j < 8; j++) acc[i][j] = 0.f;

    const int lrow = tid >> 2;          // 0..63
    const int lk   = (tid & 3) * 4;     // 0,4,8,12

    for (int k0 = 0; k0 < K; k0 += BK) {
        #pragma unroll
        for (int r = 0; r < 2; r++) {
            int row = lrow + r * 64;
            float4 v = *(const float4*)&A[(size_t)(bm + row) * K + k0 + lk];
            As[lk + 0][row] = v.x; As[lk + 1][row] = v.y;
            As[lk + 2][row] = v.z; As[lk + 3][row] = v.w;
        }
        #pragma unroll
        for (int r = 0; r < 2; r++) {
            int row = lrow + r * 64;
            float4 v = *(const float4*)&W[(size_t)(bn + row) * K + k0 + lk];
            Bs[lk + 0][row] = v.x; Bs[lk + 1][row] = v.y;
            Bs[lk + 2][row] = v.z; Bs[lk + 3][row] = v.w;
        }
        __syncthreads();

        #pragma unroll
        for (int k = 0; k < BK; k++) {
            float a[8], bv[8];
            *(float4*)&a[0]  = *(const float4*)&As[k][ty * 8];
            *(float4*)&a[4]  = *(const float4*)&As[k][ty * 8 + 4];
            *(float4*)&bv[0] = *(const float4*)&Bs[k][tx * 8];
            *(float4*)&bv[4] = *(const float4*)&Bs[k][tx * 8 + 4];
            #pragma unroll
            for (int i = 0; i < 8; i++)
                #pragma unroll
                for (int j = 0; j < 8; j++)
                    acc[i][j] = fmaf(a[i], bv[j], acc[i][j]);
        }
        __syncthreads();
    }

    #pragma unroll
    for (int i = 0; i < 8; i++) {
        int row = bm + ty * 8 + i;
        #pragma unroll
        for (int j = 0; j < 8; j++) {
            int col = bn + tx * 8 + j;
            float v = CLIP5(acc[i][j]);
            if (MODE == 0) {
                if (col < DI) out0[(size_t)row * DI + col] = v;
                else          out1[(size_t)row * DI + (col - DI)] = tanhf(v);
            } else {
                out0[(size_t)row * DM + col] = v;
            }
        }
    }
}

// ---------------------------------------------------------------------------
// Sequential SSM scan. One thread per (batch, inner-channel): 6144 threads.
// h (8 states) lives in registers; x_ssm read / y*tanh(gate) written in place.
// Consecutive threads handle consecutive i -> coalesced per-timestep access.
// ---------------------------------------------------------------------------
__global__ __launch_bounds__(128) void scan_kernel(
    const float* __restrict__ A_log, const float* __restrict__ Bm,
    const float* __restrict__ Cm)
{
    int idx = blockIdx.x * blockDim.x + threadIdx.x;   // 0..6143
    int b = idx / DI;
    int i = idx - b * DI;

    float decay[DS], bs[DS], cs[DS], h[DS];
    #pragma unroll
    for (int s = 0; s < DS; s++) {
        float a = A_log[i * DS + s];
        a = fminf(fmaxf(a, -5.0f), 0.0f);
        float Av = -__expf(a);
        Av = fminf(fmaxf(Av, -2.0f), -0.01f);
        decay[s] = Av * 0.9f;
        bs[s] = Bm[i * DS + s] * 0.1f;
        cs[s] = Cm[i * DS + s];
        h[s] = 0.f;
    }

    const float* __restrict__ xin = g_xssm + (size_t)b * SEQ * DI + i;
    const float* __restrict__ gin = g_gate + (size_t)b * SEQ * DI + i;
    float* __restrict__ yout = g_xssm + (size_t)b * SEQ * DI + i;

    #pragma unroll 4
    for (int t = 0; t < SEQ; t++) {
        float x = xin[(size_t)t * DI];
        float gt = gin[(size_t)t * DI];
        float y = 0.f;
        #pragma unroll
        for (int s = 0; s < DS; s++) {
            float hs = fmaf(h[s], decay[s], x * bs[s]);
            hs = CLIP5(hs);
            h[s] = hs;
            y = fmaf(hs, cs[s], y);
        }
        y = CLIP5(y);
        yout[(size_t)t * DI] = y * gt;
    }
}

// Note: __expf vs expf — A_log clipped to [-5,0], exp in [0.0067,1], then
// result further clipped to [-2,-0.01]; __expf max rel err ~2^-21 here, fine.

// ---------------------------------------------------------------------------
extern "C" void kernel_launch(void* const* d_in, const int* in_sizes, int n_in,
                              void* d_out, int out_size)
{
    const float* x       = (const float*)d_in[0];
    const float* W_in    = (const float*)d_in[1];
    const float* W_out   = (const float*)d_in[2];
    const float* A_log   = (const float*)d_in[3];
    const float* Bm      = (const float*)d_in[4];
    const float* Cm      = (const float*)d_in[5];
    const float* ln_in_g = (const float*)d_in[6];
    const float* ln_in_b = (const float*)d_in[7];
    const float* ln_out_g= (const float*)d_in[8];
    const float* ln_out_b= (const float*)d_in[9];
    float* out = (float*)d_out;

    float *p_xnorm, *p_xssm, *p_gate, *p_out1;
    cudaGetSymbolAddress((void**)&p_xnorm, g_xnorm);
    cudaGetSymbolAddress((void**)&p_xssm , g_xssm);
    cudaGetSymbolAddress((void**)&p_gate , g_gate);
    cudaGetSymbolAddress((void**)&p_out1 , g_out1);

    // 1) input LayerNorm
    ln_kernel<<<NTOK, 256>>>(x, ln_in_g, ln_in_b, p_xnorm);

    // 2) GEMM1: [8192 x 3072] = xnorm @ W_in^T ; clip, split, tanh(gate)
    {
        dim3 grid(NDI2 / 128, NTOK / 128);
        gemm_kernel<0><<<grid, 256>>>(p_xnorm, W_in, NTOK, NDI2, DM,
                                      p_xssm, p_gate);
    }

    // 3) sequential scan (writes y*tanh(gate) in place over x_ssm)
    scan_kernel<<<(NB * DI) / 128, 128>>>(A_log, Bm, Cm);

    // 4) GEMM2: [8192 x 1024] = (y*gate) @ W_out^T ; clip
    {
        dim3 grid(DM / 128, NTOK / 128);
        gemm_kernel<1><<<grid, 256>>>(p_xssm, W_out, NTOK, DM, DI,
                                      p_out1, nullptr);
    }

    // 5) output LayerNorm -> d_out
    ln_kernel<<<NTOK, 256>>>(p_out1, ln_out_g, ln_out_b, out);
}